// round 9
// baseline (speedup 1.0000x reference)
#include <cuda_runtime.h>
#include <cuda_bf16.h>
#include <math.h>
#include <stdint.h>

#define NN 50000
#define NE 800000
#define MPAD 50048                // 391 * 128
#define SCAN_T 256
#define SCAN_B ((NN + SCAN_T - 1) / SCAN_T)   // 196

// ---------------- scratch (static __device__, no allocation) ----------------
__device__ float g_bufA[(size_t)NN * 128];              // p128 (MLP out)
__device__ float g_bufU[(size_t)NN * 256];              // p256 (layer1 out)
__device__ float g_bufB[(size_t)NN * 64];               // u50  (layer3 pre-agg)
__device__ __nv_bfloat16 g_splitA[(size_t)MPAD * 1536]; // A''1 (K3=384) / A''3 (K3=1536)
__device__ __nv_bfloat16 g_splitB[(size_t)MPAD * 768];  // A''2 (K3=768)
__device__ __nv_bfloat16 g_w1p[256 * 384];
__device__ __nv_bfloat16 g_w2p[512 * 768];
__device__ __nv_bfloat16 g_w3p[128 * 1536];
__device__ float g_dinv[NN];
__device__ int   g_cnt[NN];
__device__ int   g_rowptr[NN + 1];
__device__ int   g_cursor[NN];
__device__ int   g_srcs[NE];
__device__ int   g_is64;
__device__ int   g_bsum[SCAN_B];
__device__ int   g_boff[SCAN_B];

// ---------------- edge dtype detection ----------------
__global__ void detect_kernel(const int* __restrict__ ei32) {
    __shared__ int any_nz;
    if (threadIdx.x == 0) any_nz = 0;
    __syncthreads();
    if (ei32[2 * threadIdx.x + 1] != 0) atomicOr(&any_nz, 1);
    __syncthreads();
    if (threadIdx.x == 0) g_is64 = (any_nz == 0) ? 1 : 0;
}
__device__ __forceinline__ int load_edge(const void* ei, int idx, int is64) {
    if (is64) return (int)((const long long*)ei)[idx];
    return ((const int*)ei)[idx];
}

// ---------------- CSR build ----------------
__global__ void zero_cnt_kernel() {
    int i = blockIdx.x * blockDim.x + threadIdx.x;
    if (i < NN) g_cnt[i] = 0;
}
__global__ void hist_kernel(const void* __restrict__ ei) {
    int e = blockIdx.x * blockDim.x + threadIdx.x;
    if (e < NE) atomicAdd(&g_cnt[load_edge(ei, NE + e, g_is64)], 1);
}
__global__ void __launch_bounds__(SCAN_T) partial_sum_kernel() {
    __shared__ int sh[SCAN_T / 32];
    int i = blockIdx.x * SCAN_T + threadIdx.x;
    int v = (i < NN) ? g_cnt[i] : 0;
    int s = v;
#pragma unroll
    for (int off = 16; off > 0; off >>= 1) s += __shfl_xor_sync(0xffffffffu, s, off);
    if ((threadIdx.x & 31) == 0) sh[threadIdx.x >> 5] = s;
    __syncthreads();
    if (threadIdx.x < SCAN_T / 32) {
        int t = sh[threadIdx.x];
#pragma unroll
        for (int off = SCAN_T / 64; off > 0; off >>= 1) t += __shfl_xor_sync(0xffffffffu, t, off, SCAN_T / 32);
        if (threadIdx.x == 0) g_bsum[blockIdx.x] = t;
    }
}
__global__ void __launch_bounds__(256) scan_sums_kernel() {
    __shared__ int s[256];
    int t = threadIdx.x;
    int v = (t < SCAN_B) ? g_bsum[t] : 0;
    s[t] = v;
    __syncthreads();
#pragma unroll
    for (int off = 1; off < 256; off <<= 1) {
        int u = (t >= off) ? s[t - off] : 0;
        __syncthreads();
        s[t] += u;
        __syncthreads();
    }
    if (t < SCAN_B) g_boff[t] = s[t] - v;
    if (t == 255) g_rowptr[NN] = s[255];
}
__global__ void __launch_bounds__(SCAN_T) write_csr_kernel() {
    __shared__ int s[SCAN_T];
    int t = threadIdx.x;
    int i = blockIdx.x * SCAN_T + t;
    int v = (i < NN) ? g_cnt[i] : 0;
    s[t] = v;
    __syncthreads();
#pragma unroll
    for (int off = 1; off < SCAN_T; off <<= 1) {
        int u = (t >= off) ? s[t - off] : 0;
        __syncthreads();
        s[t] += u;
        __syncthreads();
    }
    if (i < NN) {
        int excl = g_boff[blockIdx.x] + s[t] - v;
        g_rowptr[i] = excl;
        g_cursor[i] = excl;
        g_dinv[i]   = rsqrtf((float)v + 1.0f);
    }
}
__global__ void fill_kernel(const void* __restrict__ ei) {
    int e = blockIdx.x * blockDim.x + threadIdx.x;
    if (e < NE) {
        int is64 = g_is64;
        int d = load_edge(ei, NE + e, is64);
        int pos = atomicAdd(&g_cursor[d], 1);
        g_srcs[pos] = load_edge(ei, e, is64);
    }
}

// ---------------- weight split: W[K,N] fp32 -> W''[Npad, 3K] bf16 [hi|lo|hi]
__global__ void wsplit_kernel(const float* __restrict__ W, __nv_bfloat16* __restrict__ dst,
                              int K, int N, int Npad) {
    int idx = blockIdx.x * 256 + threadIdx.x;
    if (idx >= Npad * K) return;
    int n = idx / K, k = idx % K;
    float v = (n < N) ? W[(size_t)k * N + n] : 0.f;
    __nv_bfloat16 h = __float2bfloat16(v);
    __nv_bfloat16 l = __float2bfloat16(v - __bfloat162float(h));
    size_t base = (size_t)n * (3 * K);
    dst[base + k] = h;
    dst[base + K + k] = l;
    dst[base + 2 * K + k] = h;
}
__global__ void pad_kernel(__nv_bfloat16* __restrict__ dst, int K3) {
    int idx = blockIdx.x * 256 + threadIdx.x;
    int total = (MPAD - NN) * K3;
    if (idx < total) dst[(size_t)NN * K3 + idx] = __float2bfloat16(0.f);
}

// ---------------- fused pointwise MLP: x[N,3] -> relu stack -> p128 = h*dinv
__global__ void __launch_bounds__(128) mlp_kernel(
    const float* __restrict__ x,
    const float* __restrict__ w1, const float* __restrict__ b1,
    const float* __restrict__ w2, const float* __restrict__ b2,
    const float* __restrict__ w3, const float* __restrict__ b3)
{
    __shared__ float sw1[96], sb1[32];
    __shared__ float sw2[2048], sb2[64];
    __shared__ float sw3[8192], sb3[128];
    int t = threadIdx.x;
    for (int i = t; i < 96;   i += blockDim.x) sw1[i] = w1[i];
    for (int i = t; i < 32;   i += blockDim.x) sb1[i] = b1[i];
    for (int i = t; i < 2048; i += blockDim.x) sw2[i] = w2[i];
    for (int i = t; i < 64;   i += blockDim.x) sb2[i] = b2[i];
    for (int i = t; i < 8192; i += blockDim.x) sw3[i] = w3[i];
    for (int i = t; i < 128;  i += blockDim.x) sb3[i] = b3[i];
    __syncthreads();

    int n = blockIdx.x * blockDim.x + t;
    if (n >= NN) return;
    float x0 = x[n * 3], x1 = x[n * 3 + 1], x2 = x[n * 3 + 2];
    float dv = g_dinv[n];

    float h1[32];
#pragma unroll
    for (int j = 0; j < 32; j++)
        h1[j] = fmaxf(sb1[j] + x0 * sw1[j] + x1 * sw1[32 + j] + x2 * sw1[64 + j], 0.f);
    float h2[64];
#pragma unroll
    for (int j = 0; j < 64; j++) {
        float v = sb2[j];
#pragma unroll
        for (int k = 0; k < 32; k++) v += h1[k] * sw2[k * 64 + j];
        h2[j] = fmaxf(v, 0.f);
    }
    float* out = g_bufA + (size_t)n * 128;
#pragma unroll 4
    for (int j = 0; j < 128; j++) {
        float v = sb3[j];
#pragma unroll
        for (int k = 0; k < 64; k++) v += h2[k] * sw3[k * 128 + j];
        out[j] = fmaxf(v, 0.f) * dv;
    }
}

// ---------------- input-side aggregation -> split bf16 A'' [m][3F] = [hi|hi|lo]
template <int F>
__global__ void __launch_bounds__(256) gather_in_kernel(
    const float* __restrict__ P, __nv_bfloat16* __restrict__ out)
{
    constexpr int C = F / 32;
    int warp = threadIdx.x / 32, lane = threadIdx.x % 32;
    int n = blockIdx.x * (blockDim.x / 32) + warp;
    if (n >= NN) return;

    float acc[C];
    const float* pn = P + (size_t)n * F;
#pragma unroll
    for (int c = 0; c < C; c++) acc[c] = pn[lane + 32 * c];

    int e0 = g_rowptr[n], e1 = g_rowptr[n + 1];
    for (int eb = e0; eb < e1; eb += 32) {
        int cnt = e1 - eb; if (cnt > 32) cnt = 32;
        int s = (lane < cnt) ? g_srcs[eb + lane] : 0;
        for (int j = 0; j < cnt; j++) {
            int sj = __shfl_sync(0xffffffffu, s, j);
            const float* ps = P + (size_t)sj * F;
#pragma unroll
            for (int c = 0; c < C; c++) acc[c] += ps[lane + 32 * c];
        }
    }
    float dv = g_dinv[n];
    size_t base = (size_t)n * (3 * F);
#pragma unroll
    for (int c = 0; c < C; c++) {
        float v = dv * acc[c];
        __nv_bfloat16 h = __float2bfloat16(v);
        __nv_bfloat16 l = __float2bfloat16(v - __bfloat162float(h));
        int k = lane + 32 * c;
        out[base + k] = h;
        out[base + F + k] = h;
        out[base + 2 * F + k] = l;
    }
}

// ================= warp-level mma.sync bf16 GEMM (R7 structure) =================
// C = A[Mpad,K3] @ B[Npad,K3]^T, both K-contiguous (row.col).
// CTA tile 128 x BN, BK=32, 8 warps = 4(M) x 2(N); warp tile 32 x BN/2.
// MODE 0: fp32 = acc * dinv[m]                  (layer 3, Nout=50, BN=64)
// MODE 1: fp32 = relu(acc + bias[n]) * dinv[m]  (layer 1)
// MODE 2: split bf16 (stride 1536, halves at +512/+1024) = relu(acc + bias[n])
#define SAK 40   // smem K stride (bf16) -> conflict-free fragment loads

__device__ __forceinline__ void mma16816(float* c, const uint32_t* a, const uint32_t* b) {
    asm volatile("mma.sync.aligned.m16n8k16.row.col.f32.bf16.bf16.f32 "
        "{%0,%1,%2,%3}, {%4,%5,%6,%7}, {%8,%9}, {%0,%1,%2,%3};"
        : "+f"(c[0]), "+f"(c[1]), "+f"(c[2]), "+f"(c[3])
        : "r"(a[0]), "r"(a[1]), "r"(a[2]), "r"(a[3]), "r"(b[0]), "r"(b[1]));
}

template <int MODE, int BN>
__global__ void __launch_bounds__(256) gemm_mma(
    const __nv_bfloat16* __restrict__ A, const __nv_bfloat16* __restrict__ B,
    const float* __restrict__ bias, void* __restrict__ outp,
    int K3, int Nout)
{
    constexpr int NT = BN / 16;          // 8-wide n-tiles per warp
    __shared__ __nv_bfloat16 As[128 * SAK];
    __shared__ __nv_bfloat16 Bs[BN * SAK];
    int tid = threadIdx.x;
    int wid = tid >> 5, lane = tid & 31;
    int g = lane >> 2, tg = lane & 3;         // groupID, tid-in-group
    int wm = wid & 3, wn = wid >> 2;          // 4 M-warps x 2 N-warps
    int m0 = blockIdx.y * 128, n0 = blockIdx.x * BN;

    float c[2][NT][4];
#pragma unroll
    for (int mt = 0; mt < 2; mt++)
#pragma unroll
        for (int nt = 0; nt < NT; nt++)
#pragma unroll
            for (int i = 0; i < 4; i++) c[mt][nt][i] = 0.f;

    const __nv_bfloat16* Ag = A + (size_t)m0 * K3;
    const __nv_bfloat16* Bg = B + (size_t)n0 * K3;

    int niter = K3 >> 5;
    for (int kc = 0; kc < niter; kc++) {
        // stage A 128x32 (512 16B-segments) + B BNx32 (BN*4 segments)
#pragma unroll
        for (int i = 0; i < 2; i++) {
            int s = tid + i * 256;
            int row = s >> 2, sg = s & 3;
            *(uint4*)&As[row * SAK + sg * 8] =
                *(const uint4*)(Ag + (size_t)row * K3 + kc * 32 + sg * 8);
        }
#pragma unroll
        for (int i = 0; i < BN / 64; i++) {
            int s = tid + i * 256;
            int row = s >> 2, sg = s & 3;
            *(uint4*)&Bs[row * SAK + sg * 8] =
                *(const uint4*)(Bg + (size_t)row * K3 + kc * 32 + sg * 8);
        }
        __syncthreads();
#pragma unroll
        for (int kk = 0; kk < 32; kk += 16) {
            uint32_t af[2][4], bfr[NT][2];
#pragma unroll
            for (int mt = 0; mt < 2; mt++) {
                int base = (wm * 32 + mt * 16 + g) * SAK + kk + 2 * tg;
                af[mt][0] = *(const uint32_t*)&As[base];
                af[mt][1] = *(const uint32_t*)&As[base + 8 * SAK];
                af[mt][2] = *(const uint32_t*)&As[base + 8];
                af[mt][3] = *(const uint32_t*)&As[base + 8 * SAK + 8];
            }
#pragma unroll
            for (int nt = 0; nt < NT; nt++) {
                int base = (wn * (BN / 2) + nt * 8 + g) * SAK + kk + 2 * tg;
                bfr[nt][0] = *(const uint32_t*)&Bs[base];
                bfr[nt][1] = *(const uint32_t*)&Bs[base + 8];
            }
#pragma unroll
            for (int mt = 0; mt < 2; mt++)
#pragma unroll
                for (int nt = 0; nt < NT; nt++)
                    mma16816(c[mt][nt], af[mt], bfr[nt]);
        }
        __syncthreads();
    }

    // epilogue: rows (wm*32+mt*16+g)+{0,8}, cols (wn*(BN/2)+nt*8+2tg)+{0,1}
#pragma unroll
    for (int mt = 0; mt < 2; mt++) {
#pragma unroll
        for (int h = 0; h < 2; h++) {
            int m = m0 + wm * 32 + mt * 16 + g + h * 8;
            if (m >= NN) continue;
            float dv = g_dinv[m];
#pragma unroll
            for (int nt = 0; nt < NT; nt++) {
                int n = n0 + wn * (BN / 2) + nt * 8 + 2 * tg;
                float v0 = c[mt][nt][h * 2 + 0];
                float v1 = c[mt][nt][h * 2 + 1];
                if (MODE == 0) {
                    float* o = (float*)outp;
                    if (n < Nout)     o[(size_t)m * Nout + n]     = v0 * dv;
                    if (n + 1 < Nout) o[(size_t)m * Nout + n + 1] = v1 * dv;
                } else if (MODE == 1) {
                    float2 w;
                    w.x = fmaxf(v0 + bias[n], 0.f) * dv;
                    w.y = fmaxf(v1 + bias[n + 1], 0.f) * dv;
                    *(float2*)((float*)outp + (size_t)m * Nout + n) = w;
                } else {
                    __nv_bfloat16* o = (__nv_bfloat16*)outp;  // stride 1536
                    float a0 = fmaxf(v0 + bias[n], 0.f);
                    float a1 = fmaxf(v1 + bias[n + 1], 0.f);
                    __nv_bfloat16 h0 = __float2bfloat16(a0);
                    __nv_bfloat16 h1 = __float2bfloat16(a1);
                    __nv_bfloat16 l0 = __float2bfloat16(a0 - __bfloat162float(h0));
                    __nv_bfloat16 l1 = __float2bfloat16(a1 - __bfloat162float(h1));
                    __nv_bfloat162 hh; hh.x = h0; hh.y = h1;
                    __nv_bfloat162 ll; ll.x = l0; ll.y = l1;
                    *(__nv_bfloat162*)(o + (size_t)m * 1536 + n) = hh;
                    *(__nv_bfloat162*)(o + (size_t)m * 1536 + 512 + n) = hh;
                    *(__nv_bfloat162*)(o + (size_t)m * 1536 + 1024 + n) = ll;
                }
            }
        }
    }
}

// ---------------- final layer gather (F=50) + bias + softmax -> d_out
__global__ void __launch_bounds__(256) gather_softmax_kernel(
    const float* __restrict__ U, const float* __restrict__ bias,
    float* __restrict__ out)
{
    const int F = 50;
    int warp = threadIdx.x / 32, lane = threadIdx.x % 32;
    int n = blockIdx.x * (blockDim.x / 32) + warp;
    if (n >= NN) return;

    const float* un = U + (size_t)n * F;
    float a0 = un[lane];
    float a1 = (lane < 18) ? un[32 + lane] : 0.f;

    int e0 = g_rowptr[n], e1 = g_rowptr[n + 1];
    for (int eb = e0; eb < e1; eb += 32) {
        int cnt = e1 - eb; if (cnt > 32) cnt = 32;
        int s = (lane < cnt) ? g_srcs[eb + lane] : 0;
        for (int j = 0; j < cnt; j++) {
            int sj = __shfl_sync(0xffffffffu, s, j);
            const float* us = U + (size_t)sj * F;
            a0 += us[lane];
            if (lane < 18) a1 += us[32 + lane];
        }
    }
    float dv = g_dinv[n];
    float v0 = dv * a0 + bias[lane];
    float v1 = (lane < 18) ? (dv * a1 + bias[32 + lane]) : -INFINITY;

    float m = fmaxf(v0, v1);
#pragma unroll
    for (int off = 16; off > 0; off >>= 1)
        m = fmaxf(m, __shfl_xor_sync(0xffffffffu, m, off));
    float eA = expf(v0 - m);
    float eB = (lane < 18) ? expf(v1 - m) : 0.f;
    float s = eA + eB;
#pragma unroll
    for (int off = 16; off > 0; off >>= 1)
        s += __shfl_xor_sync(0xffffffffu, s, off);
    float inv = 1.f / s;
    out[(size_t)n * F + lane] = eA * inv;
    if (lane < 18) out[(size_t)n * F + 32 + lane] = eB * inv;
}

// ---------------- launch ----------------
extern "C" void kernel_launch(void* const* d_in, const int* in_sizes, int n_in,
                              void* d_out, int out_size)
{
    const float* x   = (const float*)d_in[0];
    const void*  ei  = d_in[1];
    const float* w1  = (const float*)d_in[2];
    const float* b1  = (const float*)d_in[3];
    const float* w2  = (const float*)d_in[4];
    const float* b2  = (const float*)d_in[5];
    const float* w3  = (const float*)d_in[6];
    const float* b3  = (const float*)d_in[7];
    const float* g1w = (const float*)d_in[8];
    const float* g1b = (const float*)d_in[9];
    const float* g2w = (const float*)d_in[10];
    const float* g2b = (const float*)d_in[11];
    const float* g3w = (const float*)d_in[12];
    const float* g3b = (const float*)d_in[13];
    float* out = (float*)d_out;

    float *pA, *pU, *pB;
    __nv_bfloat16 *pSA, *pSB, *pW1, *pW2, *pW3;
    cudaGetSymbolAddress((void**)&pA,  g_bufA);
    cudaGetSymbolAddress((void**)&pU,  g_bufU);
    cudaGetSymbolAddress((void**)&pB,  g_bufB);
    cudaGetSymbolAddress((void**)&pSA, g_splitA);
    cudaGetSymbolAddress((void**)&pSB, g_splitB);
    cudaGetSymbolAddress((void**)&pW1, g_w1p);
    cudaGetSymbolAddress((void**)&pW2, g_w2p);
    cudaGetSymbolAddress((void**)&pW3, g_w3p);

    // CSR + dinv
    detect_kernel<<<1, 1024>>>((const int*)ei);
    zero_cnt_kernel<<<(NN + 255) / 256, 256>>>();
    hist_kernel<<<(NE + 255) / 256, 256>>>(ei);
    partial_sum_kernel<<<SCAN_B, SCAN_T>>>();
    scan_sums_kernel<<<1, 256>>>();
    write_csr_kernel<<<SCAN_B, SCAN_T>>>();
    fill_kernel<<<(NE + 255) / 256, 256>>>(ei);

    // weight splits + A'' row padding
    wsplit_kernel<<<(256 * 128 + 255) / 256, 256>>>(g1w, pW1, 128, 256, 256);
    wsplit_kernel<<<(512 * 256 + 255) / 256, 256>>>(g2w, pW2, 256, 512, 512);
    wsplit_kernel<<<(128 * 512 + 255) / 256, 256>>>(g3w, pW3, 512, 50, 128);
    pad_kernel<<<((MPAD - NN) * 384  + 255) / 256, 256>>>(pSA, 384);
    pad_kernel<<<((MPAD - NN) * 768  + 255) / 256, 256>>>(pSB, 768);
    pad_kernel<<<((MPAD - NN) * 1536 + 255) / 256, 256>>>(pSA, 1536);

    // MLP -> p128
    mlp_kernel<<<(NN + 127) / 128, 128>>>(x, w1, b1, w2, b2, w3, b3);

    const int gw = 6250;

    // Layer 1: gather p128 -> A''1 (splitA, K3=384); gemm -> p256 fp32 (bufU)
    gather_in_kernel<128><<<gw, 256>>>(pA, pSA);
    {
        dim3 grid(2, MPAD / 128);
        gemm_mma<1, 128><<<grid, 256>>>(pSA, pW1, g1b, pU, 384, 256);
    }
    // Layer 2: gather p256 -> A''2 (splitB, K3=768); gemm -> A''3 split bf16 (splitA)
    gather_in_kernel<256><<<gw, 256>>>(pU, pSB);
    {
        dim3 grid(4, MPAD / 128);
        gemm_mma<2, 128><<<grid, 256>>>(pSB, pW2, g2b, pSA, 768, 512);
    }
    // Layer 3: gemm A''3 @ W3 -> u50 fp32 (*dinv, bufB), BN=64; gather+softmax -> out
    {
        dim3 grid(1, MPAD / 128);
        gemm_mma<0, 64><<<grid, 256>>>(pSA, pW3, g3b, pB, 1536, 50);
    }
    gather_softmax_kernel<<<gw, 256>>>(pB, g3b, out);
}

// round 11
// speedup vs baseline: 1.3413x; 1.3413x over previous
#include <cuda_runtime.h>
#include <cuda_bf16.h>
#include <math.h>
#include <stdint.h>

#define NN 50000
#define NE 800000
#define MPAD 50048                // 391 * 128
#define SCAN_T 256
#define SCAN_B ((NN + SCAN_T - 1) / SCAN_T)   // 196

// ---------------- scratch (static __device__, no allocation) ----------------
__device__ float g_bufA[(size_t)NN * 128];              // p128 (MLP out)
__device__ float g_bufU[(size_t)NN * 256];              // p256 (layer1 out)
__device__ float g_bufB[(size_t)NN * 64];               // u50 (stride 64, layer3 pre-agg)
__device__ __nv_bfloat16 g_splitA[(size_t)MPAD * 1536]; // A''1 (K3=384) / A''3 (K3=1536)
__device__ __nv_bfloat16 g_splitB[(size_t)MPAD * 768];  // A''2 (K3=768)
__device__ __nv_bfloat16 g_w1p[256 * 384];
__device__ __nv_bfloat16 g_w2p[512 * 768];
__device__ __nv_bfloat16 g_w3p[128 * 1536];
__device__ float g_dinv[NN];
__device__ int   g_cnt[NN];
__device__ int   g_rowptr[NN + 1];
__device__ int   g_cursor[NN];
__device__ int   g_srcs[NE];
__device__ int   g_is64;
__device__ int   g_bsum[SCAN_B];
__device__ int   g_boff[SCAN_B];

// ---------------- edge dtype detection ----------------
__global__ void detect_kernel(const int* __restrict__ ei32) {
    __shared__ int any_nz;
    if (threadIdx.x == 0) any_nz = 0;
    __syncthreads();
    if (ei32[2 * threadIdx.x + 1] != 0) atomicOr(&any_nz, 1);
    __syncthreads();
    if (threadIdx.x == 0) g_is64 = (any_nz == 0) ? 1 : 0;
}
__device__ __forceinline__ int load_edge(const void* ei, int idx, int is64) {
    if (is64) return (int)((const long long*)ei)[idx];
    return ((const int*)ei)[idx];
}

// ---------------- CSR build ----------------
__global__ void zero_cnt_kernel() {
    int i = blockIdx.x * blockDim.x + threadIdx.x;
    if (i < NN) g_cnt[i] = 0;
}
__global__ void hist_kernel(const void* __restrict__ ei) {
    int e = blockIdx.x * blockDim.x + threadIdx.x;
    if (e < NE) atomicAdd(&g_cnt[load_edge(ei, NE + e, g_is64)], 1);
}
__global__ void __launch_bounds__(SCAN_T) partial_sum_kernel() {
    __shared__ int sh[SCAN_T / 32];
    int i = blockIdx.x * SCAN_T + threadIdx.x;
    int v = (i < NN) ? g_cnt[i] : 0;
    int s = v;
#pragma unroll
    for (int off = 16; off > 0; off >>= 1) s += __shfl_xor_sync(0xffffffffu, s, off);
    if ((threadIdx.x & 31) == 0) sh[threadIdx.x >> 5] = s;
    __syncthreads();
    if (threadIdx.x < SCAN_T / 32) {
        int t = sh[threadIdx.x];
#pragma unroll
        for (int off = SCAN_T / 64; off > 0; off >>= 1) t += __shfl_xor_sync(0xffffffffu, t, off, SCAN_T / 32);
        if (threadIdx.x == 0) g_bsum[blockIdx.x] = t;
    }
}
__global__ void __launch_bounds__(256) scan_sums_kernel() {
    __shared__ int s[256];
    int t = threadIdx.x;
    int v = (t < SCAN_B) ? g_bsum[t] : 0;
    s[t] = v;
    __syncthreads();
#pragma unroll
    for (int off = 1; off < 256; off <<= 1) {
        int u = (t >= off) ? s[t - off] : 0;
        __syncthreads();
        s[t] += u;
        __syncthreads();
    }
    if (t < SCAN_B) g_boff[t] = s[t] - v;
    if (t == 255) g_rowptr[NN] = s[255];
}
__global__ void __launch_bounds__(SCAN_T) write_csr_kernel() {
    __shared__ int s[SCAN_T];
    int t = threadIdx.x;
    int i = blockIdx.x * SCAN_T + t;
    int v = (i < NN) ? g_cnt[i] : 0;
    s[t] = v;
    __syncthreads();
#pragma unroll
    for (int off = 1; off < SCAN_T; off <<= 1) {
        int u = (t >= off) ? s[t - off] : 0;
        __syncthreads();
        s[t] += u;
        __syncthreads();
    }
    if (i < NN) {
        int excl = g_boff[blockIdx.x] + s[t] - v;
        g_rowptr[i] = excl;
        g_cursor[i] = excl;
        g_dinv[i]   = rsqrtf((float)v + 1.0f);
    }
}
__global__ void fill_kernel(const void* __restrict__ ei) {
    int e = blockIdx.x * blockDim.x + threadIdx.x;
    if (e < NE) {
        int is64 = g_is64;
        int d = load_edge(ei, NE + e, is64);
        int pos = atomicAdd(&g_cursor[d], 1);
        g_srcs[pos] = load_edge(ei, e, is64);
    }
}

// ---------------- weight split: W[K,N] fp32 -> W''[Npad, 3K] bf16 [hi|lo|hi]
__global__ void wsplit_kernel(const float* __restrict__ W, __nv_bfloat16* __restrict__ dst,
                              int K, int N, int Npad) {
    int idx = blockIdx.x * 256 + threadIdx.x;
    if (idx >= Npad * K) return;
    int n = idx / K, k = idx % K;
    float v = (n < N) ? W[(size_t)k * N + n] : 0.f;
    __nv_bfloat16 h = __float2bfloat16(v);
    __nv_bfloat16 l = __float2bfloat16(v - __bfloat162float(h));
    size_t base = (size_t)n * (3 * K);
    dst[base + k] = h;
    dst[base + K + k] = l;
    dst[base + 2 * K + k] = h;
}
__global__ void pad_kernel(__nv_bfloat16* __restrict__ dst, int K3) {
    int idx = blockIdx.x * 256 + threadIdx.x;
    int total = (MPAD - NN) * K3;
    if (idx < total) dst[(size_t)NN * K3 + idx] = __float2bfloat16(0.f);
}

// ---------------- fused pointwise MLP: x[N,3] -> relu stack -> p128 = h*dinv
__global__ void __launch_bounds__(128) mlp_kernel(
    const float* __restrict__ x,
    const float* __restrict__ w1, const float* __restrict__ b1,
    const float* __restrict__ w2, const float* __restrict__ b2,
    const float* __restrict__ w3, const float* __restrict__ b3)
{
    __shared__ float sw1[96], sb1[32];
    __shared__ float sw2[2048], sb2[64];
    __shared__ float sw3[8192], sb3[128];
    int t = threadIdx.x;
    for (int i = t; i < 96;   i += blockDim.x) sw1[i] = w1[i];
    for (int i = t; i < 32;   i += blockDim.x) sb1[i] = b1[i];
    for (int i = t; i < 2048; i += blockDim.x) sw2[i] = w2[i];
    for (int i = t; i < 64;   i += blockDim.x) sb2[i] = b2[i];
    for (int i = t; i < 8192; i += blockDim.x) sw3[i] = w3[i];
    for (int i = t; i < 128;  i += blockDim.x) sb3[i] = b3[i];
    __syncthreads();

    int n = blockIdx.x * blockDim.x + t;
    if (n >= NN) return;
    float x0 = x[n * 3], x1 = x[n * 3 + 1], x2 = x[n * 3 + 2];
    float dv = g_dinv[n];

    float h1[32];
#pragma unroll
    for (int j = 0; j < 32; j++)
        h1[j] = fmaxf(sb1[j] + x0 * sw1[j] + x1 * sw1[32 + j] + x2 * sw1[64 + j], 0.f);
    float h2[64];
#pragma unroll
    for (int j = 0; j < 64; j++) {
        float v = sb2[j];
#pragma unroll
        for (int k = 0; k < 32; k++) v += h1[k] * sw2[k * 64 + j];
        h2[j] = fmaxf(v, 0.f);
    }
    float* out = g_bufA + (size_t)n * 128;
#pragma unroll 4
    for (int j = 0; j < 128; j++) {
        float v = sb3[j];
#pragma unroll
        for (int k = 0; k < 64; k++) v += h2[k] * sw3[k * 128 + j];
        out[j] = fmaxf(v, 0.f) * dv;
    }
}

// ---------------- input-side aggregation -> split bf16 A'' [m][3F] = [hi|hi|lo]
template <int F>
__global__ void __launch_bounds__(256) gather_in_kernel(
    const float* __restrict__ P, __nv_bfloat16* __restrict__ out)
{
    constexpr int C = F / 32;
    int warp = threadIdx.x / 32, lane = threadIdx.x % 32;
    int n = blockIdx.x * (blockDim.x / 32) + warp;
    if (n >= NN) return;

    float acc[C];
    const float* pn = P + (size_t)n * F;
#pragma unroll
    for (int c = 0; c < C; c++) acc[c] = pn[lane + 32 * c];

    int e0 = g_rowptr[n], e1 = g_rowptr[n + 1];
    for (int eb = e0; eb < e1; eb += 32) {
        int cnt = e1 - eb; if (cnt > 32) cnt = 32;
        int s = (lane < cnt) ? g_srcs[eb + lane] : 0;
        for (int j = 0; j < cnt; j++) {
            int sj = __shfl_sync(0xffffffffu, s, j);
            const float* ps = P + (size_t)sj * F;
#pragma unroll
            for (int c = 0; c < C; c++) acc[c] += ps[lane + 32 * c];
        }
    }
    float dv = g_dinv[n];
    size_t base = (size_t)n * (3 * F);
#pragma unroll
    for (int c = 0; c < C; c++) {
        float v = dv * acc[c];
        __nv_bfloat16 h = __float2bfloat16(v);
        __nv_bfloat16 l = __float2bfloat16(v - __bfloat162float(h));
        int k = lane + 32 * c;
        out[base + k] = h;
        out[base + F + k] = h;
        out[base + 2 * F + k] = l;
    }
}

// ================= warp-level mma.sync bf16 GEMM (exact R7 structure) =================
// C = A[Mpad,K3] @ B[Npad,K3]^T, both K-contiguous (row.col).
// CTA 128x128, BK=32, 8 warps = 4(M) x 2(N), warp tile 32x64.
// MODE 0: fp32 stride 64 = acc * dinv[m]        (layer 3, Nout=50)
// MODE 1: fp32 = relu(acc + bias[n]) * dinv[m]  (layer 1)
// MODE 2: split bf16 (stride 1536, halves at +512/+1024) = relu(acc + bias[n])
#define SAK 40   // smem K stride (bf16) -> conflict-free 32-bit fragment loads

__device__ __forceinline__ void mma16816(float* c, const uint32_t* a, const uint32_t* b) {
    asm volatile("mma.sync.aligned.m16n8k16.row.col.f32.bf16.bf16.f32 "
        "{%0,%1,%2,%3}, {%4,%5,%6,%7}, {%8,%9}, {%0,%1,%2,%3};"
        : "+f"(c[0]), "+f"(c[1]), "+f"(c[2]), "+f"(c[3])
        : "r"(a[0]), "r"(a[1]), "r"(a[2]), "r"(a[3]), "r"(b[0]), "r"(b[1]));
}

template <int MODE>
__global__ void __launch_bounds__(256) gemm_mma(
    const __nv_bfloat16* __restrict__ A, const __nv_bfloat16* __restrict__ B,
    const float* __restrict__ bias, void* __restrict__ outp,
    int K3, int Nout)
{
    __shared__ __nv_bfloat16 As[128 * SAK];
    __shared__ __nv_bfloat16 Bs[128 * SAK];
    int tid = threadIdx.x;
    int wid = tid >> 5, lane = tid & 31;
    int g = lane >> 2, tg = lane & 3;         // groupID, tid-in-group
    int wm = wid & 3, wn = wid >> 2;          // 4 M-warps x 2 N-warps
    int m0 = blockIdx.y * 128, n0 = blockIdx.x * 128;

    float c[2][8][4];
#pragma unroll
    for (int mt = 0; mt < 2; mt++)
#pragma unroll
        for (int nt = 0; nt < 8; nt++)
#pragma unroll
            for (int i = 0; i < 4; i++) c[mt][nt][i] = 0.f;

    const __nv_bfloat16* Ag = A + (size_t)m0 * K3;
    const __nv_bfloat16* Bg = B + (size_t)n0 * K3;

    int niter = K3 >> 5;
    for (int kc = 0; kc < niter; kc++) {
        // stage 128x32 bf16 tiles: 512 16B-segments each, 2 per thread
#pragma unroll
        for (int i = 0; i < 2; i++) {
            int s = tid + i * 256;
            int row = s >> 2, sg = s & 3;
            *(uint4*)&As[row * SAK + sg * 8] =
                *(const uint4*)(Ag + (size_t)row * K3 + kc * 32 + sg * 8);
            *(uint4*)&Bs[row * SAK + sg * 8] =
                *(const uint4*)(Bg + (size_t)row * K3 + kc * 32 + sg * 8);
        }
        __syncthreads();
#pragma unroll
        for (int kk = 0; kk < 32; kk += 16) {
            uint32_t af[2][4], bfr[8][2];
#pragma unroll
            for (int mt = 0; mt < 2; mt++) {
                int base = (wm * 32 + mt * 16 + g) * SAK + kk + 2 * tg;
                af[mt][0] = *(const uint32_t*)&As[base];
                af[mt][1] = *(const uint32_t*)&As[base + 8 * SAK];
                af[mt][2] = *(const uint32_t*)&As[base + 8];
                af[mt][3] = *(const uint32_t*)&As[base + 8 * SAK + 8];
            }
#pragma unroll
            for (int nt = 0; nt < 8; nt++) {
                int base = (wn * 64 + nt * 8 + g) * SAK + kk + 2 * tg;
                bfr[nt][0] = *(const uint32_t*)&Bs[base];
                bfr[nt][1] = *(const uint32_t*)&Bs[base + 8];
            }
#pragma unroll
            for (int mt = 0; mt < 2; mt++)
#pragma unroll
                for (int nt = 0; nt < 8; nt++)
                    mma16816(c[mt][nt], af[mt], bfr[nt]);
        }
        __syncthreads();
    }

    // epilogue: rows (wm*32+mt*16+g)+{0,8}, cols (wn*64+nt*8+2tg)+{0,1}
#pragma unroll
    for (int mt = 0; mt < 2; mt++) {
#pragma unroll
        for (int h = 0; h < 2; h++) {
            int m = m0 + wm * 32 + mt * 16 + g + h * 8;
            if (m >= NN) continue;
            float dv = g_dinv[m];
#pragma unroll
            for (int nt = 0; nt < 8; nt++) {
                int n = n0 + wn * 64 + nt * 8 + 2 * tg;
                float v0 = c[mt][nt][h * 2 + 0];
                float v1 = c[mt][nt][h * 2 + 1];
                if (MODE == 0) {
                    // u50 with row stride 64 (256B-aligned rows); cols >= 50 are
                    // garbage-free: only n < 50 stores, rest of row never read
                    if (n < Nout) {
                        float2 w; w.x = v0 * dv; w.y = v1 * dv;
                        if (n + 1 < Nout)
                            *(float2*)((float*)outp + (size_t)m * 64 + n) = w;
                        else
                            ((float*)outp)[(size_t)m * 64 + n] = w.x;
                    }
                } else if (MODE == 1) {
                    float2 w;
                    w.x = fmaxf(v0 + bias[n], 0.f) * dv;
                    w.y = fmaxf(v1 + bias[n + 1], 0.f) * dv;
                    *(float2*)((float*)outp + (size_t)m * Nout + n) = w;
                } else {
                    __nv_bfloat16* o = (__nv_bfloat16*)outp;  // stride 1536
                    float a0 = fmaxf(v0 + bias[n], 0.f);
                    float a1 = fmaxf(v1 + bias[n + 1], 0.f);
                    __nv_bfloat16 h0 = __float2bfloat16(a0);
                    __nv_bfloat16 h1 = __float2bfloat16(a1);
                    __nv_bfloat16 l0 = __float2bfloat16(a0 - __bfloat162float(h0));
                    __nv_bfloat16 l1 = __float2bfloat16(a1 - __bfloat162float(h1));
                    __nv_bfloat162 hh; hh.x = h0; hh.y = h1;
                    __nv_bfloat162 ll; ll.x = l0; ll.y = l1;
                    *(__nv_bfloat162*)(o + (size_t)m * 1536 + n) = hh;
                    *(__nv_bfloat162*)(o + (size_t)m * 1536 + 512 + n) = hh;
                    *(__nv_bfloat162*)(o + (size_t)m * 1536 + 1024 + n) = ll;
                }
            }
        }
    }
}

// ---------------- final layer gather (F=50, stride 64) + bias + softmax -> d_out
__global__ void __launch_bounds__(256) gather_softmax_kernel(
    const float* __restrict__ U, const float* __restrict__ bias,
    float* __restrict__ out)
{
    int warp = threadIdx.x / 32, lane = threadIdx.x % 32;
    int n = blockIdx.x * (blockDim.x / 32) + warp;
    if (n >= NN) return;

    const float* un = U + (size_t)n * 64;
    float a0 = un[lane];
    float a1 = (lane < 18) ? un[32 + lane] : 0.f;

    int e0 = g_rowptr[n], e1 = g_rowptr[n + 1];
    for (int eb = e0; eb < e1; eb += 32) {
        int cnt = e1 - eb; if (cnt > 32) cnt = 32;
        int s = (lane < cnt) ? g_srcs[eb + lane] : 0;
        for (int j = 0; j < cnt; j++) {
            int sj = __shfl_sync(0xffffffffu, s, j);
            const float* us = U + (size_t)sj * 64;
            a0 += us[lane];
            if (lane < 18) a1 += us[32 + lane];
        }
    }
    float dv = g_dinv[n];
    float v0 = dv * a0 + bias[lane];
    float v1 = (lane < 18) ? (dv * a1 + bias[32 + lane]) : -INFINITY;

    float m = fmaxf(v0, v1);
#pragma unroll
    for (int off = 16; off > 0; off >>= 1)
        m = fmaxf(m, __shfl_xor_sync(0xffffffffu, m, off));
    float eA = expf(v0 - m);
    float eB = (lane < 18) ? expf(v1 - m) : 0.f;
    float s = eA + eB;
#pragma unroll
    for (int off = 16; off > 0; off >>= 1)
        s += __shfl_xor_sync(0xffffffffu, s, off);
    float inv = 1.f / s;
    out[(size_t)n * 50 + lane] = eA * inv;
    if (lane < 18) out[(size_t)n * 50 + 32 + lane] = eB * inv;
}

// ---------------- launch ----------------
extern "C" void kernel_launch(void* const* d_in, const int* in_sizes, int n_in,
                              void* d_out, int out_size)
{
    const float* x   = (const float*)d_in[0];
    const void*  ei  = d_in[1];
    const float* w1  = (const float*)d_in[2];
    const float* b1  = (const float*)d_in[3];
    const float* w2  = (const float*)d_in[4];
    const float* b2  = (const float*)d_in[5];
    const float* w3  = (const float*)d_in[6];
    const float* b3  = (const float*)d_in[7];
    const float* g1w = (const float*)d_in[8];
    const float* g1b = (const float*)d_in[9];
    const float* g2w = (const float*)d_in[10];
    const float* g2b = (const float*)d_in[11];
    const float* g3w = (const float*)d_in[12];
    const float* g3b = (const float*)d_in[13];
    float* out = (float*)d_out;

    float *pA, *pU, *pB;
    __nv_bfloat16 *pSA, *pSB, *pW1, *pW2, *pW3;
    cudaGetSymbolAddress((void**)&pA,  g_bufA);
    cudaGetSymbolAddress((void**)&pU,  g_bufU);
    cudaGetSymbolAddress((void**)&pB,  g_bufB);
    cudaGetSymbolAddress((void**)&pSA, g_splitA);
    cudaGetSymbolAddress((void**)&pSB, g_splitB);
    cudaGetSymbolAddress((void**)&pW1, g_w1p);
    cudaGetSymbolAddress((void**)&pW2, g_w2p);
    cudaGetSymbolAddress((void**)&pW3, g_w3p);

    // CSR + dinv
    detect_kernel<<<1, 1024>>>((const int*)ei);
    zero_cnt_kernel<<<(NN + 255) / 256, 256>>>();
    hist_kernel<<<(NE + 255) / 256, 256>>>(ei);
    partial_sum_kernel<<<SCAN_B, SCAN_T>>>();
    scan_sums_kernel<<<1, 256>>>();
    write_csr_kernel<<<SCAN_B, SCAN_T>>>();
    fill_kernel<<<(NE + 255) / 256, 256>>>(ei);

    // weight splits + A'' row padding
    wsplit_kernel<<<(256 * 128 + 255) / 256, 256>>>(g1w, pW1, 128, 256, 256);
    wsplit_kernel<<<(512 * 256 + 255) / 256, 256>>>(g2w, pW2, 256, 512, 512);
    wsplit_kernel<<<(128 * 512 + 255) / 256, 256>>>(g3w, pW3, 512, 50, 128);
    pad_kernel<<<((MPAD - NN) * 384  + 255) / 256, 256>>>(pSA, 384);
    pad_kernel<<<((MPAD - NN) * 768  + 255) / 256, 256>>>(pSB, 768);
    pad_kernel<<<((MPAD - NN) * 1536 + 255) / 256, 256>>>(pSA, 1536);

    // MLP -> p128
    mlp_kernel<<<(NN + 127) / 128, 128>>>(x, w1, b1, w2, b2, w3, b3);

    const int gw = 6250;

    // Layer 1: gather p128 -> A''1 (splitA, K3=384); gemm -> p256 fp32 (bufU)
    gather_in_kernel<128><<<gw, 256>>>(pA, pSA);
    {
        dim3 grid(2, MPAD / 128);
        gemm_mma<1><<<grid, 256>>>(pSA, pW1, g1b, pU, 384, 256);
    }
    // Layer 2: gather p256 -> A''2 (splitB, K3=768); gemm -> A''3 split bf16 (splitA)
    gather_in_kernel<256><<<gw, 256>>>(pU, pSB);
    {
        dim3 grid(4, MPAD / 128);
        gemm_mma<2><<<grid, 256>>>(pSB, pW2, g2b, pSA, 768, 512);
    }
    // Layer 3: gemm A''3 @ W3 -> u50 (stride 64, *dinv, bufB); gather+softmax -> out
    {
        dim3 grid(1, MPAD / 128);
        gemm_mma<0><<<grid, 256>>>(pSA, pW3, g3b, pB, 1536, 50);
    }
    gather_softmax_kernel<<<gw, 256>>>(pB, g3b, out);
}

// round 12
// speedup vs baseline: 1.9290x; 1.4381x over previous
#include <cuda_runtime.h>
#include <cuda_bf16.h>
#include <math.h>
#include <stdint.h>

#define NN 50000
#define NE 800000
#define MPAD 50048                // 391 * 128
#define SCAN_T 256
#define SCAN_B ((NN + SCAN_T - 1) / SCAN_T)   // 196

// ---------------- scratch (static __device__, no allocation) ----------------
__device__ float g_bufA[(size_t)NN * 128];        // p128 (MLP out)
__device__ float g_bufU[(size_t)NN * 256];        // p256 (layer1 out)
__device__ float g_bufB[(size_t)NN * 64];         // u50 (stride 64)
__device__ float g_tA[(size_t)MPAD * 512];        // A1 (stride 128) then A3 (stride 512), tf32
__device__ float g_tB[(size_t)MPAD * 256];        // A2 (stride 256), tf32
__device__ float g_w1t[256 * 128];                // W1^T tf32 [n][k]
__device__ float g_w2t[512 * 256];
__device__ float g_w3t[128 * 512];                // N padded 50 -> 128
__device__ float g_dinv[NN];
__device__ int   g_cnt[NN];
__device__ int   g_rowptr[NN + 1];
__device__ int   g_cursor[NN];
__device__ int   g_srcs[NE];
__device__ int   g_is64;
__device__ int   g_bsum[SCAN_B];
__device__ int   g_boff[SCAN_B];

__device__ __forceinline__ float to_tf32(float x) {
    float r;
    asm("cvt.rna.tf32.f32 %0, %1;" : "=f"(r) : "f"(x));
    return r;
}

// ---------------- edge dtype detection ----------------
__global__ void detect_kernel(const int* __restrict__ ei32) {
    __shared__ int any_nz;
    if (threadIdx.x == 0) any_nz = 0;
    __syncthreads();
    if (ei32[2 * threadIdx.x + 1] != 0) atomicOr(&any_nz, 1);
    __syncthreads();
    if (threadIdx.x == 0) g_is64 = (any_nz == 0) ? 1 : 0;
}
__device__ __forceinline__ int load_edge(const void* ei, int idx, int is64) {
    if (is64) return (int)((const long long*)ei)[idx];
    return ((const int*)ei)[idx];
}

// ---------------- CSR build ----------------
__global__ void zero_cnt_kernel() {
    int i = blockIdx.x * blockDim.x + threadIdx.x;
    if (i < NN) g_cnt[i] = 0;
}
__global__ void hist_kernel(const void* __restrict__ ei) {
    int e = blockIdx.x * blockDim.x + threadIdx.x;
    if (e < NE) atomicAdd(&g_cnt[load_edge(ei, NE + e, g_is64)], 1);
}
__global__ void __launch_bounds__(SCAN_T) partial_sum_kernel() {
    __shared__ int sh[SCAN_T / 32];
    int i = blockIdx.x * SCAN_T + threadIdx.x;
    int v = (i < NN) ? g_cnt[i] : 0;
    int s = v;
#pragma unroll
    for (int off = 16; off > 0; off >>= 1) s += __shfl_xor_sync(0xffffffffu, s, off);
    if ((threadIdx.x & 31) == 0) sh[threadIdx.x >> 5] = s;
    __syncthreads();
    if (threadIdx.x < SCAN_T / 32) {
        int t = sh[threadIdx.x];
#pragma unroll
        for (int off = SCAN_T / 64; off > 0; off >>= 1) t += __shfl_xor_sync(0xffffffffu, t, off, SCAN_T / 32);
        if (threadIdx.x == 0) g_bsum[blockIdx.x] = t;
    }
}
__global__ void __launch_bounds__(256) scan_sums_kernel() {
    __shared__ int s[256];
    int t = threadIdx.x;
    int v = (t < SCAN_B) ? g_bsum[t] : 0;
    s[t] = v;
    __syncthreads();
#pragma unroll
    for (int off = 1; off < 256; off <<= 1) {
        int u = (t >= off) ? s[t - off] : 0;
        __syncthreads();
        s[t] += u;
        __syncthreads();
    }
    if (t < SCAN_B) g_boff[t] = s[t] - v;
    if (t == 255) g_rowptr[NN] = s[255];
}
__global__ void __launch_bounds__(SCAN_T) write_csr_kernel() {
    __shared__ int s[SCAN_T];
    int t = threadIdx.x;
    int i = blockIdx.x * SCAN_T + t;
    int v = (i < NN) ? g_cnt[i] : 0;
    s[t] = v;
    __syncthreads();
#pragma unroll
    for (int off = 1; off < SCAN_T; off <<= 1) {
        int u = (t >= off) ? s[t - off] : 0;
        __syncthreads();
        s[t] += u;
        __syncthreads();
    }
    if (i < NN) {
        int excl = g_boff[blockIdx.x] + s[t] - v;
        g_rowptr[i] = excl;
        g_cursor[i] = excl;
        g_dinv[i]   = rsqrtf((float)v + 1.0f);
    }
}
__global__ void fill_kernel(const void* __restrict__ ei) {
    int e = blockIdx.x * blockDim.x + threadIdx.x;
    if (e < NE) {
        int is64 = g_is64;
        int d = load_edge(ei, NE + e, is64);
        int pos = atomicAdd(&g_cursor[d], 1);
        g_srcs[pos] = load_edge(ei, e, is64);
    }
}

// ---------------- weight prep: W[K,N] fp32 -> Wt[Npad][K] tf32-rounded fp32
__global__ void wprep_kernel(const float* __restrict__ W, float* __restrict__ dst,
                             int K, int N, int Npad) {
    int idx = blockIdx.x * 256 + threadIdx.x;
    if (idx >= Npad * K) return;
    int n = idx / K, k = idx % K;
    float v = (n < N) ? W[(size_t)k * N + n] : 0.f;
    dst[(size_t)n * K + k] = to_tf32(v);
}
__global__ void padf_kernel(float* __restrict__ dst, int count) {
    int idx = blockIdx.x * 256 + threadIdx.x;
    if (idx < count) dst[idx] = 0.f;
}

// ---------------- fused pointwise MLP: x[N,3] -> relu stack -> p128 = h*dinv
__global__ void __launch_bounds__(128) mlp_kernel(
    const float* __restrict__ x,
    const float* __restrict__ w1, const float* __restrict__ b1,
    const float* __restrict__ w2, const float* __restrict__ b2,
    const float* __restrict__ w3, const float* __restrict__ b3)
{
    __shared__ float sw1[96], sb1[32];
    __shared__ float sw2[2048], sb2[64];
    __shared__ float sw3[8192], sb3[128];
    int t = threadIdx.x;
    for (int i = t; i < 96;   i += blockDim.x) sw1[i] = w1[i];
    for (int i = t; i < 32;   i += blockDim.x) sb1[i] = b1[i];
    for (int i = t; i < 2048; i += blockDim.x) sw2[i] = w2[i];
    for (int i = t; i < 64;   i += blockDim.x) sb2[i] = b2[i];
    for (int i = t; i < 8192; i += blockDim.x) sw3[i] = w3[i];
    for (int i = t; i < 128;  i += blockDim.x) sb3[i] = b3[i];
    __syncthreads();

    int n = blockIdx.x * blockDim.x + t;
    if (n >= NN) return;
    float x0 = x[n * 3], x1 = x[n * 3 + 1], x2 = x[n * 3 + 2];
    float dv = g_dinv[n];

    float h1[32];
#pragma unroll
    for (int j = 0; j < 32; j++)
        h1[j] = fmaxf(sb1[j] + x0 * sw1[j] + x1 * sw1[32 + j] + x2 * sw1[64 + j], 0.f);
    float h2[64];
#pragma unroll
    for (int j = 0; j < 64; j++) {
        float v = sb2[j];
#pragma unroll
        for (int k = 0; k < 32; k++) v += h1[k] * sw2[k * 64 + j];
        h2[j] = fmaxf(v, 0.f);
    }
    float* out = g_bufA + (size_t)n * 128;
#pragma unroll 4
    for (int j = 0; j < 128; j++) {
        float v = sb3[j];
#pragma unroll
        for (int k = 0; k < 64; k++) v += h2[k] * sw3[k * 128 + j];
        out[j] = fmaxf(v, 0.f) * dv;
    }
}

// ---------------- input-side aggregation -> tf32-rounded fp32 A[m][F]
template <int F>
__global__ void __launch_bounds__(256) gather_in_kernel(
    const float* __restrict__ P, float* __restrict__ out)
{
    constexpr int C = F / 32;
    int warp = threadIdx.x / 32, lane = threadIdx.x % 32;
    int n = blockIdx.x * (blockDim.x / 32) + warp;
    if (n >= NN) return;

    float acc[C];
    const float* pn = P + (size_t)n * F;
#pragma unroll
    for (int c = 0; c < C; c++) acc[c] = pn[lane + 32 * c];

    int e0 = g_rowptr[n], e1 = g_rowptr[n + 1];
    for (int eb = e0; eb < e1; eb += 32) {
        int cnt = e1 - eb; if (cnt > 32) cnt = 32;
        int s = (lane < cnt) ? g_srcs[eb + lane] : 0;
        for (int j = 0; j < cnt; j++) {
            int sj = __shfl_sync(0xffffffffu, s, j);
            const float* ps = P + (size_t)sj * F;
#pragma unroll
            for (int c = 0; c < C; c++) acc[c] += ps[lane + 32 * c];
        }
    }
    float dv = g_dinv[n];
#pragma unroll
    for (int c = 0; c < C; c++)
        out[(size_t)n * F + lane + 32 * c] = to_tf32(dv * acc[c]);
}

// ================= warp-level mma.sync TF32 GEMM =================
// C = A[Mpad,K] @ B[Npad,K]^T, both K-contiguous tf32-rounded fp32 (row.col).
// CTA 128x128, BK=32, 8 warps = 4(M) x 2(N), warp tile 32x64, m16n8k8.
// MODE 0: fp32 stride 64 = acc * dinv[m]        (layer 3, Nout=50)
// MODE 1: fp32 = relu(acc + bias[n]) * dinv[m]  (layer 1 -> p256)
// MODE 2: tf32 fp32 stride 512 = relu(acc+b)    (layer 2 -> A3)
#define STR 36   // fp32 smem K stride -> conflict-free fragment loads (4g+tg distinct)

__device__ __forceinline__ void mma_tf32(float* c, const uint32_t* a, const uint32_t* b) {
    asm volatile("mma.sync.aligned.m16n8k8.row.col.f32.tf32.tf32.f32 "
        "{%0,%1,%2,%3}, {%4,%5,%6,%7}, {%8,%9}, {%0,%1,%2,%3};"
        : "+f"(c[0]), "+f"(c[1]), "+f"(c[2]), "+f"(c[3])
        : "r"(a[0]), "r"(a[1]), "r"(a[2]), "r"(a[3]), "r"(b[0]), "r"(b[1]));
}

template <int MODE>
__global__ void __launch_bounds__(256) gemm_tf32(
    const float* __restrict__ A, const float* __restrict__ B,
    const float* __restrict__ bias, float* __restrict__ outp,
    int K, int Nout)
{
    __shared__ float As[128 * STR];
    __shared__ float Bs[128 * STR];
    int tid = threadIdx.x;
    int wid = tid >> 5, lane = tid & 31;
    int g = lane >> 2, tg = lane & 3;         // groupID, tid-in-group
    int wm = wid & 3, wn = wid >> 2;          // 4 M-warps x 2 N-warps
    int m0 = blockIdx.y * 128, n0 = blockIdx.x * 128;

    float c[2][8][4];
#pragma unroll
    for (int mt = 0; mt < 2; mt++)
#pragma unroll
        for (int nt = 0; nt < 8; nt++)
#pragma unroll
            for (int i = 0; i < 4; i++) c[mt][nt][i] = 0.f;

    const float* Ag = A + (size_t)m0 * K;
    const float* Bg = B + (size_t)n0 * K;

    int niter = K >> 5;
    for (int kc = 0; kc < niter; kc++) {
        // stage 128x32 fp32 tiles: 1024 16B-segments each, 4 per thread
#pragma unroll
        for (int i = 0; i < 4; i++) {
            int s = tid + i * 256;
            int row = s >> 3, sg = s & 7;
            *(uint4*)&As[row * STR + sg * 4] =
                *(const uint4*)(Ag + (size_t)row * K + kc * 32 + sg * 4);
            *(uint4*)&Bs[row * STR + sg * 4] =
                *(const uint4*)(Bg + (size_t)row * K + kc * 32 + sg * 4);
        }
        __syncthreads();
#pragma unroll
        for (int kk = 0; kk < 32; kk += 8) {
            uint32_t af[2][4], bfr[8][2];
#pragma unroll
            for (int mt = 0; mt < 2; mt++) {
                int base = (wm * 32 + mt * 16 + g) * STR + kk + tg;
                af[mt][0] = *(const uint32_t*)&As[base];
                af[mt][1] = *(const uint32_t*)&As[base + 8 * STR];
                af[mt][2] = *(const uint32_t*)&As[base + 4];
                af[mt][3] = *(const uint32_t*)&As[base + 8 * STR + 4];
            }
#pragma unroll
            for (int nt = 0; nt < 8; nt++) {
                int base = (wn * 64 + nt * 8 + g) * STR + kk + tg;
                bfr[nt][0] = *(const uint32_t*)&Bs[base];
                bfr[nt][1] = *(const uint32_t*)&Bs[base + 4];
            }
#pragma unroll
            for (int mt = 0; mt < 2; mt++)
#pragma unroll
                for (int nt = 0; nt < 8; nt++)
                    mma_tf32(c[mt][nt], af[mt], bfr[nt]);
        }
        __syncthreads();
    }

    // epilogue: rows (wm*32+mt*16+g)+{0,8}, cols (wn*64+nt*8+2tg)+{0,1}
#pragma unroll
    for (int mt = 0; mt < 2; mt++) {
#pragma unroll
        for (int h = 0; h < 2; h++) {
            int m = m0 + wm * 32 + mt * 16 + g + h * 8;
            if (m >= NN) continue;
            float dv = g_dinv[m];
#pragma unroll
            for (int nt = 0; nt < 8; nt++) {
                int n = n0 + wn * 64 + nt * 8 + 2 * tg;
                float v0 = c[mt][nt][h * 2 + 0];
                float v1 = c[mt][nt][h * 2 + 1];
                if (MODE == 0) {
                    if (n < Nout) {
                        float2 w; w.x = v0 * dv; w.y = v1 * dv;
                        if (n + 1 < Nout)
                            *(float2*)(outp + (size_t)m * 64 + n) = w;
                        else
                            outp[(size_t)m * 64 + n] = w.x;
                    }
                } else if (MODE == 1) {
                    float2 w;
                    w.x = fmaxf(v0 + bias[n], 0.f) * dv;
                    w.y = fmaxf(v1 + bias[n + 1], 0.f) * dv;
                    *(float2*)(outp + (size_t)m * Nout + n) = w;
                } else {
                    float2 w;
                    w.x = to_tf32(fmaxf(v0 + bias[n], 0.f));
                    w.y = to_tf32(fmaxf(v1 + bias[n + 1], 0.f));
                    *(float2*)(outp + (size_t)m * 512 + n) = w;
                }
            }
        }
    }
}

// ---------------- final layer gather (F=50, stride 64) + bias + softmax -> d_out
__global__ void __launch_bounds__(256) gather_softmax_kernel(
    const float* __restrict__ U, const float* __restrict__ bias,
    float* __restrict__ out)
{
    int warp = threadIdx.x / 32, lane = threadIdx.x % 32;
    int n = blockIdx.x * (blockDim.x / 32) + warp;
    if (n >= NN) return;

    const float* un = U + (size_t)n * 64;
    float a0 = un[lane];
    float a1 = (lane < 18) ? un[32 + lane] : 0.f;

    int e0 = g_rowptr[n], e1 = g_rowptr[n + 1];
    for (int eb = e0; eb < e1; eb += 32) {
        int cnt = e1 - eb; if (cnt > 32) cnt = 32;
        int s = (lane < cnt) ? g_srcs[eb + lane] : 0;
        for (int j = 0; j < cnt; j++) {
            int sj = __shfl_sync(0xffffffffu, s, j);
            const float* us = U + (size_t)sj * 64;
            a0 += us[lane];
            if (lane < 18) a1 += us[32 + lane];
        }
    }
    float dv = g_dinv[n];
    float v0 = dv * a0 + bias[lane];
    float v1 = (lane < 18) ? (dv * a1 + bias[32 + lane]) : -INFINITY;

    float m = fmaxf(v0, v1);
#pragma unroll
    for (int off = 16; off > 0; off >>= 1)
        m = fmaxf(m, __shfl_xor_sync(0xffffffffu, m, off));
    float eA = expf(v0 - m);
    float eB = (lane < 18) ? expf(v1 - m) : 0.f;
    float s = eA + eB;
#pragma unroll
    for (int off = 16; off > 0; off >>= 1)
        s += __shfl_xor_sync(0xffffffffu, s, off);
    float inv = 1.f / s;
    out[(size_t)n * 50 + lane] = eA * inv;
    if (lane < 18) out[(size_t)n * 50 + 32 + lane] = eB * inv;
}

// ---------------- launch ----------------
extern "C" void kernel_launch(void* const* d_in, const int* in_sizes, int n_in,
                              void* d_out, int out_size)
{
    const float* x   = (const float*)d_in[0];
    const void*  ei  = d_in[1];
    const float* w1  = (const float*)d_in[2];
    const float* b1  = (const float*)d_in[3];
    const float* w2  = (const float*)d_in[4];
    const float* b2  = (const float*)d_in[5];
    const float* w3  = (const float*)d_in[6];
    const float* b3  = (const float*)d_in[7];
    const float* g1w = (const float*)d_in[8];
    const float* g1b = (const float*)d_in[9];
    const float* g2w = (const float*)d_in[10];
    const float* g2b = (const float*)d_in[11];
    const float* g3w = (const float*)d_in[12];
    const float* g3b = (const float*)d_in[13];
    float* out = (float*)d_out;

    float *pA, *pU, *pB, *ptA, *ptB, *pW1, *pW2, *pW3;
    cudaGetSymbolAddress((void**)&pA,  g_bufA);
    cudaGetSymbolAddress((void**)&pU,  g_bufU);
    cudaGetSymbolAddress((void**)&pB,  g_bufB);
    cudaGetSymbolAddress((void**)&ptA, g_tA);
    cudaGetSymbolAddress((void**)&ptB, g_tB);
    cudaGetSymbolAddress((void**)&pW1, g_w1t);
    cudaGetSymbolAddress((void**)&pW2, g_w2t);
    cudaGetSymbolAddress((void**)&pW3, g_w3t);

    // CSR + dinv
    detect_kernel<<<1, 1024>>>((const int*)ei);
    zero_cnt_kernel<<<(NN + 255) / 256, 256>>>();
    hist_kernel<<<(NE + 255) / 256, 256>>>(ei);
    partial_sum_kernel<<<SCAN_B, SCAN_T>>>();
    scan_sums_kernel<<<1, 256>>>();
    write_csr_kernel<<<SCAN_B, SCAN_T>>>();
    fill_kernel<<<(NE + 255) / 256, 256>>>(ei);

    // weight prep (tf32-rounded, transposed) + A-pad zeroing
    wprep_kernel<<<(256 * 128 + 255) / 256, 256>>>(g1w, pW1, 128, 256, 256);
    wprep_kernel<<<(512 * 256 + 255) / 256, 256>>>(g2w, pW2, 256, 512, 512);
    wprep_kernel<<<(128 * 512 + 255) / 256, 256>>>(g3w, pW3, 512, 50, 128);
    padf_kernel<<<((MPAD - NN) * 128 + 255) / 256, 256>>>(ptA + (size_t)NN * 128, (MPAD - NN) * 128);
    padf_kernel<<<((MPAD - NN) * 256 + 255) / 256, 256>>>(ptB + (size_t)NN * 256, (MPAD - NN) * 256);
    padf_kernel<<<((MPAD - NN) * 512 + 255) / 256, 256>>>(ptA + (size_t)NN * 512, (MPAD - NN) * 512);

    // MLP -> p128
    mlp_kernel<<<(NN + 127) / 128, 128>>>(x, w1, b1, w2, b2, w3, b3);

    const int gw = 6250;

    // Layer 1: gather p128 -> A1 (tA stride 128); gemm -> p256 fp32 (bufU)
    gather_in_kernel<128><<<gw, 256>>>(pA, ptA);
    {
        dim3 grid(2, MPAD / 128);
        gemm_tf32<1><<<grid, 256>>>(ptA, pW1, g1b, pU, 128, 256);
    }
    // Layer 2: gather p256 -> A2 (tB stride 256); gemm -> A3 tf32 (tA stride 512)
    gather_in_kernel<256><<<gw, 256>>>(pU, ptB);
    {
        dim3 grid(4, MPAD / 128);
        gemm_tf32<2><<<grid, 256>>>(ptB, pW2, g2b, ptA, 256, 512);
    }
    // Layer 3: gemm A3 @ W3t -> u50 (stride 64, *dinv, bufB); gather+softmax -> out
    {
        dim3 grid(1, MPAD / 128);
        gemm_tf32<0><<<grid, 256>>>(ptA, pW3, g3b, pB, 512, 50);
    }
    gather_softmax_kernel<<<gw, 256>>>(pB, g3b, out);
}

// round 14
// speedup vs baseline: 2.1153x; 1.0966x over previous
#include <cuda_runtime.h>
#include <cuda_bf16.h>
#include <math.h>
#include <stdint.h>

#define NN 50000
#define NE 800000
#define MPAD 50048                // 391 * 128
#define SCAN_T 256
#define SCAN_B ((NN + SCAN_T - 1) / SCAN_T)   // 196

// ---------------- scratch (static __device__, no allocation) ----------------
__device__ __nv_bfloat16 g_p128[(size_t)NN * 128];  // MLP out, bf16
__device__ __nv_bfloat16 g_p256[(size_t)NN * 256];  // layer1 out, bf16
__device__ float g_bufB[(size_t)NN * 64];           // u50 (stride 64)
__device__ float g_tA[(size_t)MPAD * 512];          // A1 (stride 128) then A3 (stride 512), tf32
__device__ float g_tB[(size_t)MPAD * 256];          // A2 (stride 256), tf32
__device__ float g_w1t[256 * 128];                  // W1^T tf32 [n][k]
__device__ float g_w2t[512 * 256];
__device__ float g_w3t[128 * 512];                  // N padded 50 -> 128
__device__ float g_dinv[NN];
__device__ int   g_cnt[NN];
__device__ int   g_rowptr[NN + 1];
__device__ int   g_cursor[NN];
__device__ int   g_srcs[NE];
__device__ int   g_is64;
__device__ int   g_bsum[SCAN_B];
__device__ int   g_boff[SCAN_B];

__device__ __forceinline__ float to_tf32(float x) {
    float r;
    asm("cvt.rna.tf32.f32 %0, %1;" : "=f"(r) : "f"(x));
    return r;
}

// ---------------- edge dtype detection ----------------
__global__ void detect_kernel(const int* __restrict__ ei32) {
    __shared__ int any_nz;
    if (threadIdx.x == 0) any_nz = 0;
    __syncthreads();
    if (ei32[2 * threadIdx.x + 1] != 0) atomicOr(&any_nz, 1);
    __syncthreads();
    if (threadIdx.x == 0) g_is64 = (any_nz == 0) ? 1 : 0;
}
__device__ __forceinline__ int load_edge(const void* ei, int idx, int is64) {
    if (is64) return (int)((const long long*)ei)[idx];
    return ((const int*)ei)[idx];
}

// ---------------- CSR build ----------------
__global__ void zero_cnt_kernel() {
    int i = blockIdx.x * blockDim.x + threadIdx.x;
    if (i < NN) g_cnt[i] = 0;
}
__global__ void hist_kernel(const void* __restrict__ ei) {
    int e = blockIdx.x * blockDim.x + threadIdx.x;
    if (e < NE) atomicAdd(&g_cnt[load_edge(ei, NE + e, g_is64)], 1);
}
__global__ void __launch_bounds__(SCAN_T) partial_sum_kernel() {
    __shared__ int sh[SCAN_T / 32];
    int i = blockIdx.x * SCAN_T + threadIdx.x;
    int v = (i < NN) ? g_cnt[i] : 0;
    int s = v;
#pragma unroll
    for (int off = 16; off > 0; off >>= 1) s += __shfl_xor_sync(0xffffffffu, s, off);
    if ((threadIdx.x & 31) == 0) sh[threadIdx.x >> 5] = s;
    __syncthreads();
    if (threadIdx.x < SCAN_T / 32) {
        int t = sh[threadIdx.x];
#pragma unroll
        for (int off = SCAN_T / 64; off > 0; off >>= 1) t += __shfl_xor_sync(0xffffffffu, t, off, SCAN_T / 32);
        if (threadIdx.x == 0) g_bsum[blockIdx.x] = t;
    }
}
__global__ void __launch_bounds__(256) scan_sums_kernel() {
    __shared__ int s[256];
    int t = threadIdx.x;
    int v = (t < SCAN_B) ? g_bsum[t] : 0;
    s[t] = v;
    __syncthreads();
#pragma unroll
    for (int off = 1; off < 256; off <<= 1) {
        int u = (t >= off) ? s[t - off] : 0;
        __syncthreads();
        s[t] += u;
        __syncthreads();
    }
    if (t < SCAN_B) g_boff[t] = s[t] - v;
    if (t == 255) g_rowptr[NN] = s[255];
}
__global__ void __launch_bounds__(SCAN_T) write_csr_kernel() {
    __shared__ int s[SCAN_T];
    int t = threadIdx.x;
    int i = blockIdx.x * SCAN_T + t;
    int v = (i < NN) ? g_cnt[i] : 0;
    s[t] = v;
    __syncthreads();
#pragma unroll
    for (int off = 1; off < SCAN_T; off <<= 1) {
        int u = (t >= off) ? s[t - off] : 0;
        __syncthreads();
        s[t] += u;
        __syncthreads();
    }
    if (i < NN) {
        int excl = g_boff[blockIdx.x] + s[t] - v;
        g_rowptr[i] = excl;
        g_cursor[i] = excl;
        g_dinv[i]   = rsqrtf((float)v + 1.0f);
    }
}
__global__ void fill_kernel(const void* __restrict__ ei) {
    int e = blockIdx.x * blockDim.x + threadIdx.x;
    if (e < NE) {
        int is64 = g_is64;
        int d = load_edge(ei, NE + e, is64);
        int pos = atomicAdd(&g_cursor[d], 1);
        g_srcs[pos] = load_edge(ei, e, is64);
    }
}

// ---------------- weight prep: W[K,N] fp32 -> Wt[Npad][K] tf32-rounded fp32
__global__ void wprep_kernel(const float* __restrict__ W, float* __restrict__ dst,
                             int K, int N, int Npad) {
    int idx = blockIdx.x * 256 + threadIdx.x;
    if (idx >= Npad * K) return;
    int n = idx / K, k = idx % K;
    float v = (n < N) ? W[(size_t)k * N + n] : 0.f;
    dst[(size_t)n * K + k] = to_tf32(v);
}
__global__ void padf_kernel(float* __restrict__ dst, int count) {
    int idx = blockIdx.x * 256 + threadIdx.x;
    if (idx < count) dst[idx] = 0.f;
}

// ---------------- fused pointwise MLP: x[N,3] -> relu stack -> p128 bf16 = h*dinv
__global__ void __launch_bounds__(128) mlp_kernel(
    const float* __restrict__ x,
    const float* __restrict__ w1, const float* __restrict__ b1,
    const float* __restrict__ w2, const float* __restrict__ b2,
    const float* __restrict__ w3, const float* __restrict__ b3)
{
    __shared__ float sw1[96], sb1[32];
    __shared__ float sw2[2048], sb2[64];
    __shared__ float sw3[8192], sb3[128];
    int t = threadIdx.x;
    for (int i = t; i < 96;   i += blockDim.x) sw1[i] = w1[i];
    for (int i = t; i < 32;   i += blockDim.x) sb1[i] = b1[i];
    for (int i = t; i < 2048; i += blockDim.x) sw2[i] = w2[i];
    for (int i = t; i < 64;   i += blockDim.x) sb2[i] = b2[i];
    for (int i = t; i < 8192; i += blockDim.x) sw3[i] = w3[i];
    for (int i = t; i < 128;  i += blockDim.x) sb3[i] = b3[i];
    __syncthreads();

    int n = blockIdx.x * blockDim.x + t;
    if (n >= NN) return;
    float x0 = x[n * 3], x1 = x[n * 3 + 1], x2 = x[n * 3 + 2];
    float dv = g_dinv[n];

    float h1[32];
#pragma unroll
    for (int j = 0; j < 32; j++)
        h1[j] = fmaxf(sb1[j] + x0 * sw1[j] + x1 * sw1[32 + j] + x2 * sw1[64 + j], 0.f);
    float h2[64];
#pragma unroll
    for (int j = 0; j < 64; j++) {
        float v = sb2[j];
#pragma unroll
        for (int k = 0; k < 32; k++) v += h1[k] * sw2[k * 64 + j];
        h2[j] = fmaxf(v, 0.f);
    }
    __nv_bfloat16* out = g_p128 + (size_t)n * 128;
#pragma unroll 2
    for (int j = 0; j < 128; j += 2) {
        float v0 = sb3[j], v1 = sb3[j + 1];
#pragma unroll
        for (int k = 0; k < 64; k++) {
            v0 += h2[k] * sw3[k * 128 + j];
            v1 += h2[k] * sw3[k * 128 + j + 1];
        }
        __nv_bfloat162 w;
        w.x = __float2bfloat16(fmaxf(v0, 0.f) * dv);
        w.y = __float2bfloat16(fmaxf(v1, 0.f) * dv);
        *(__nv_bfloat162*)(out + j) = w;
    }
}

// ---------------- input-side aggregation (bf16 in) -> tf32 fp32 A[m][F]
// lane handles paired cols 2*lane + 64*c  (128B coalesced bf162 loads)
template <int F>
__global__ void __launch_bounds__(256) gather_in_kernel(
    const __nv_bfloat16* __restrict__ P, float* __restrict__ out)
{
    constexpr int C2 = F / 64;
    int warp = threadIdx.x / 32, lane = threadIdx.x % 32;
    int n = blockIdx.x * (blockDim.x / 32) + warp;
    if (n >= NN) return;

    float accx[C2], accy[C2];
    const __nv_bfloat16* pn = P + (size_t)n * F;
#pragma unroll
    for (int c = 0; c < C2; c++) {
        float2 v = __bfloat1622float2(*(const __nv_bfloat162*)(pn + 2 * lane + 64 * c));
        accx[c] = v.x; accy[c] = v.y;
    }

    int e0 = g_rowptr[n], e1 = g_rowptr[n + 1];
    for (int eb = e0; eb < e1; eb += 32) {
        int cnt = e1 - eb; if (cnt > 32) cnt = 32;
        int s = (lane < cnt) ? g_srcs[eb + lane] : 0;
        for (int j = 0; j < cnt; j++) {
            int sj = __shfl_sync(0xffffffffu, s, j);
            const __nv_bfloat16* ps = P + (size_t)sj * F;
#pragma unroll
            for (int c = 0; c < C2; c++) {
                float2 v = __bfloat1622float2(*(const __nv_bfloat162*)(ps + 2 * lane + 64 * c));
                accx[c] += v.x; accy[c] += v.y;
            }
        }
    }
    float dv = g_dinv[n];
#pragma unroll
    for (int c = 0; c < C2; c++) {
        float2 w;
        w.x = to_tf32(dv * accx[c]);
        w.y = to_tf32(dv * accy[c]);
        *(float2*)(out + (size_t)n * F + 2 * lane + 64 * c) = w;
    }
}

// ================= warp-level mma.sync TF32 GEMM =================
// C = A[Mpad,K] @ B[Npad,K]^T, both K-contiguous tf32-rounded fp32 (row.col).
// CTA 128x128, BK=32, 8 warps = 4(M) x 2(N), warp tile 32x64, m16n8k8.
// MODE 0: fp32 stride 64 = acc * dinv[m]          (layer 3, Nout=50)
// MODE 1: bf16 stride 256 = relu(acc+b) * dinv[m] (layer 1 -> p256)
// MODE 2: tf32 fp32 stride 512 = relu(acc+b)      (layer 2 -> A3)
#define STR 36   // fp32 smem K stride -> conflict-free fragment loads

__device__ __forceinline__ void mma_tf32(float* c, const uint32_t* a, const uint32_t* b) {
    asm volatile("mma.sync.aligned.m16n8k8.row.col.f32.tf32.tf32.f32 "
        "{%0,%1,%2,%3}, {%4,%5,%6,%7}, {%8,%9}, {%0,%1,%2,%3};"
        : "+f"(c[0]), "+f"(c[1]), "+f"(c[2]), "+f"(c[3])
        : "r"(a[0]), "r"(a[1]), "r"(a[2]), "r"(a[3]), "r"(b[0]), "r"(b[1]));
}

template <int MODE>
__global__ void __launch_bounds__(256) gemm_tf32(
    const float* __restrict__ A, const float* __restrict__ B,
    const float* __restrict__ bias, void* __restrict__ outp,
    int K, int Nout)
{
    __shared__ float As[128 * STR];
    __shared__ float Bs[128 * STR];
    int tid = threadIdx.x;
    int wid = tid >> 5, lane = tid & 31;
    int g = lane >> 2, tg = lane & 3;         // groupID, tid-in-group
    int wm = wid & 3, wn = wid >> 2;          // 4 M-warps x 2 N-warps
    int m0 = blockIdx.y * 128, n0 = blockIdx.x * 128;

    float c[2][8][4];
#pragma unroll
    for (int mt = 0; mt < 2; mt++)
#pragma unroll
        for (int nt = 0; nt < 8; nt++)
#pragma unroll
            for (int i = 0; i < 4; i++) c[mt][nt][i] = 0.f;

    const float* Ag = A + (size_t)m0 * K;
    const float* Bg = B + (size_t)n0 * K;

    int niter = K >> 5;
    for (int kc = 0; kc < niter; kc++) {
#pragma unroll
        for (int i = 0; i < 4; i++) {
            int s = tid + i * 256;
            int row = s >> 3, sg = s & 7;
            *(uint4*)&As[row * STR + sg * 4] =
                *(const uint4*)(Ag + (size_t)row * K + kc * 32 + sg * 4);
            *(uint4*)&Bs[row * STR + sg * 4] =
                *(const uint4*)(Bg + (size_t)row * K + kc * 32 + sg * 4);
        }
        __syncthreads();
#pragma unroll
        for (int kk = 0; kk < 32; kk += 8) {
            uint32_t af[2][4], bfr[8][2];
#pragma unroll
            for (int mt = 0; mt < 2; mt++) {
                int base = (wm * 32 + mt * 16 + g) * STR + kk + tg;
                af[mt][0] = *(const uint32_t*)&As[base];
                af[mt][1] = *(const uint32_t*)&As[base + 8 * STR];
                af[mt][2] = *(const uint32_t*)&As[base + 4];
                af[mt][3] = *(const uint32_t*)&As[base + 8 * STR + 4];
            }
#pragma unroll
            for (int nt = 0; nt < 8; nt++) {
                int base = (wn * 64 + nt * 8 + g) * STR + kk + tg;
                bfr[nt][0] = *(const uint32_t*)&Bs[base];
                bfr[nt][1] = *(const uint32_t*)&Bs[base + 4];
            }
#pragma unroll
            for (int mt = 0; mt < 2; mt++)
#pragma unroll
                for (int nt = 0; nt < 8; nt++)
                    mma_tf32(c[mt][nt], af[mt], bfr[nt]);
        }
        __syncthreads();
    }

    // epilogue: rows (wm*32+mt*16+g)+{0,8}, cols (wn*64+nt*8+2tg)+{0,1}
#pragma unroll
    for (int mt = 0; mt < 2; mt++) {
#pragma unroll
        for (int h = 0; h < 2; h++) {
            int m = m0 + wm * 32 + mt * 16 + g + h * 8;
            if (m >= NN) continue;
            float dv = g_dinv[m];
#pragma unroll
            for (int nt = 0; nt < 8; nt++) {
                int n = n0 + wn * 64 + nt * 8 + 2 * tg;
                float v0 = c[mt][nt][h * 2 + 0];
                float v1 = c[mt][nt][h * 2 + 1];
                if (MODE == 0) {
                    float* o = (float*)outp;
                    if (n < Nout) {
                        float2 w; w.x = v0 * dv; w.y = v1 * dv;
                        if (n + 1 < Nout)
                            *(float2*)(o + (size_t)m * 64 + n) = w;
                        else
                            o[(size_t)m * 64 + n] = w.x;
                    }
                } else if (MODE == 1) {
                    __nv_bfloat16* o = (__nv_bfloat16*)outp;   // p256 bf16
                    __nv_bfloat162 w;
                    w.x = __float2bfloat16(fmaxf(v0 + bias[n], 0.f) * dv);
                    w.y = __float2bfloat16(fmaxf(v1 + bias[n + 1], 0.f) * dv);
                    *(__nv_bfloat162*)(o + (size_t)m * Nout + n) = w;
                } else {
                    float* o = (float*)outp;                   // A3 stride 512
                    float2 w;
                    w.x = to_tf32(fmaxf(v0 + bias[n], 0.f));
                    w.y = to_tf32(fmaxf(v1 + bias[n + 1], 0.f));
                    *(float2*)(o + (size_t)m * 512 + n) = w;
                }
            }
        }
    }
}

// ---------------- final layer gather (F=50, stride 64) + bias + softmax -> d_out
__global__ void __launch_bounds__(256) gather_softmax_kernel(
    const float* __restrict__ U, const float* __restrict__ bias,
    float* __restrict__ out)
{
    int warp = threadIdx.x / 32, lane = threadIdx.x % 32;
    int n = blockIdx.x * (blockDim.x / 32) + warp;
    if (n >= NN) return;

    const float* un = U + (size_t)n * 64;
    float a0 = un[lane];
    float a1 = (lane < 18) ? un[32 + lane] : 0.f;

    int e0 = g_rowptr[n], e1 = g_rowptr[n + 1];
    for (int eb = e0; eb < e1; eb += 32) {
        int cnt = e1 - eb; if (cnt > 32) cnt = 32;
        int s = (lane < cnt) ? g_srcs[eb + lane] : 0;
        for (int j = 0; j < cnt; j++) {
            int sj = __shfl_sync(0xffffffffu, s, j);
            const float* us = U + (size_t)sj * 64;
            a0 += us[lane];
            if (lane < 18) a1 += us[32 + lane];
        }
    }
    float dv = g_dinv[n];
    float v0 = dv * a0 + bias[lane];
    float v1 = (lane < 18) ? (dv * a1 + bias[32 + lane]) : -INFINITY;

    float m = fmaxf(v0, v1);
#pragma unroll
    for (int off = 16; off > 0; off >>= 1)
        m = fmaxf(m, __shfl_xor_sync(0xffffffffu, m, off));
    float eA = expf(v0 - m);
    float eB = (lane < 18) ? expf(v1 - m) : 0.f;
    float s = eA + eB;
#pragma unroll
    for (int off = 16; off > 0; off >>= 1)
        s += __shfl_xor_sync(0xffffffffu, s, off);
    float inv = 1.f / s;
    out[(size_t)n * 50 + lane] = eA * inv;
    if (lane < 18) out[(size_t)n * 50 + 32 + lane] = eB * inv;
}

// ---------------- launch ----------------
extern "C" void kernel_launch(void* const* d_in, const int* in_sizes, int n_in,
                              void* d_out, int out_size)
{
    const float* x   = (const float*)d_in[0];
    const void*  ei  = d_in[1];
    const float* w1  = (const float*)d_in[2];
    const float* b1  = (const float*)d_in[3];
    const float* w2  = (const float*)d_in[4];
    const float* b2  = (const float*)d_in[5];
    const float* w3  = (const float*)d_in[6];
    const float* b3  = (const float*)d_in[7];
    const float* g1w = (const float*)d_in[8];
    const float* g1b = (const float*)d_in[9];
    const float* g2w = (const float*)d_in[10];
    const float* g2b = (const float*)d_in[11];
    const float* g3w = (const float*)d_in[12];
    const float* g3b = (const float*)d_in[13];
    float* out = (float*)d_out;

    float *pB, *ptA, *ptB, *pW1, *pW2, *pW3;
    __nv_bfloat16 *pP128, *pP256;
    cudaGetSymbolAddress((void**)&pP128, g_p128);
    cudaGetSymbolAddress((void**)&pP256, g_p256);
    cudaGetSymbolAddress((void**)&pB,  g_bufB);
    cudaGetSymbolAddress((void**)&ptA, g_tA);
    cudaGetSymbolAddress((void**)&ptB, g_tB);
    cudaGetSymbolAddress((void**)&pW1, g_w1t);
    cudaGetSymbolAddress((void**)&pW2, g_w2t);
    cudaGetSymbolAddress((void**)&pW3, g_w3t);

    // CSR + dinv
    detect_kernel<<<1, 1024>>>((const int*)ei);
    zero_cnt_kernel<<<(NN + 255) / 256, 256>>>();
    hist_kernel<<<(NE + 255) / 256, 256>>>(ei);
    partial_sum_kernel<<<SCAN_B, SCAN_T>>>();
    scan_sums_kernel<<<1, 256>>>();
    write_csr_kernel<<<SCAN_B, SCAN_T>>>();
    fill_kernel<<<(NE + 255) / 256, 256>>>(ei);

    // weight prep (tf32-rounded, transposed) + A-pad zeroing
    wprep_kernel<<<(256 * 128 + 255) / 256, 256>>>(g1w, pW1, 128, 256, 256);
    wprep_kernel<<<(512 * 256 + 255) / 256, 256>>>(g2w, pW2, 256, 512, 512);
    wprep_kernel<<<(128 * 512 + 255) / 256, 256>>>(g3w, pW3, 512, 50, 128);
    padf_kernel<<<((MPAD - NN) * 128 + 255) / 256, 256>>>(ptA + (size_t)NN * 128, (MPAD - NN) * 128);
    padf_kernel<<<((MPAD - NN) * 256 + 255) / 256, 256>>>(ptB + (size_t)NN * 256, (MPAD - NN) * 256);
    padf_kernel<<<((MPAD - NN) * 512 + 255) / 256, 256>>>(ptA + (size_t)NN * 512, (MPAD - NN) * 512);

    // MLP -> p128 bf16
    mlp_kernel<<<(NN + 127) / 128, 128>>>(x, w1, b1, w2, b2, w3, b3);

    const int gw = 6250;

    // Layer 1: gather p128 bf16 -> A1 (tA stride 128); gemm -> p256 bf16
    gather_in_kernel<128><<<gw, 256>>>(pP128, ptA);
    {
        dim3 grid(2, MPAD / 128);
        gemm_tf32<1><<<grid, 256>>>(ptA, pW1, g1b, pP256, 128, 256);
    }
    // Layer 2: gather p256 bf16 -> A2 (tB stride 256); gemm -> A3 tf32 (tA stride 512)
    gather_in_kernel<256><<<gw, 256>>>(pP256, ptB);
    {
        dim3 grid(4, MPAD / 128);
        gemm_tf32<2><<<grid, 256>>>(ptB, pW2, g2b, ptA, 256, 512);
    }
    // Layer 3: gemm A3 @ W3t -> u50 (stride 64, *dinv); gather+softmax -> out
    {
        dim3 grid(1, MPAD / 128);
        gemm_tf32<0><<<grid, 256>>>(ptA, pW3, g3b, pB, 512, 50);
    }
    gather_softmax_kernel<<<gw, 256>>>(pB, g3b, out);
}